// round 7
// baseline (speedup 1.0000x reference)
#include <cuda_runtime.h>
#include <cuda_fp16.h>
#include <cstdint>

#define T_SEQ 2048
#define HID   4096
#define QKV_N 6144
#define HD    128
#define NHEADS 32
#define ATTN_SCALE 0.08838834764831845f   // 128^-0.5

// GEMM: BM=BN=128, BK=32 (fp16), 3 tiles/stage (Ah,Al,Bh), 3 stages, 2 CTAs/SM
#define TILE_B 8192
#define STG_BYTES (3 * TILE_B)
#define GEMM_SMEM (3 * STG_BYTES)

// Attention: Qh,Ql,Kh,Kl,Vh,Vl 64x128 fp16 (16KB each) + P 64x64 fp16 (8KB)
#define ATTN_SMEM (6 * 16384 + 8192)

extern __shared__ char dyn_smem[];

// ---------------------------------------------------------------------------
// Scratch (allocation-free rule: __device__ globals)
// ---------------------------------------------------------------------------
__device__ float g_qkv[(size_t)T_SEQ * QKV_N];
__device__ __align__(16) __half g_ah[(size_t)T_SEQ * HID];    // GEMM A hi
__device__ __align__(16) __half g_al[(size_t)T_SEQ * HID];    // GEMM A lo
__device__ __align__(16) __half g_wqh[(size_t)QKV_N * HID];   // Wqkv^T fp16 [N,K]
__device__ __align__(16) __half g_woh[(size_t)HID * HID];     // Wo^T fp16
__device__ __align__(16) __half g_qh[(size_t)T_SEQ * HID];    // roped+scaled Q hi
__device__ __align__(16) __half g_ql[(size_t)T_SEQ * HID];
__device__ __align__(16) __half g_kh[(size_t)T_SEQ * 1024];   // roped K hi
__device__ __align__(16) __half g_kl[(size_t)T_SEQ * 1024];
__device__ __align__(16) __half g_vh[(size_t)T_SEQ * 1024];   // V hi
__device__ __align__(16) __half g_vl[(size_t)T_SEQ * 1024];

// ---------------------------------------------------------------------------
// helpers
// ---------------------------------------------------------------------------
__device__ __forceinline__ uint32_t smem_u32(const void* p) {
  uint32_t a;
  asm("{ .reg .u64 t; cvta.to.shared.u64 t, %1; cvt.u32.u64 %0, t; }"
      : "=r"(a) : "l"(p));
  return a;
}

__device__ __forceinline__ void cp16(uint32_t dst, const void* src) {
  asm volatile("cp.async.cg.shared.global [%0], [%1], 16;"
               :: "r"(dst), "l"(src) : "memory");
}

__device__ __forceinline__ void ldsm4(unsigned r[4], uint32_t addr) {
  asm volatile("ldmatrix.sync.aligned.m8n8.x4.shared.b16 {%0,%1,%2,%3}, [%4];"
               : "=r"(r[0]), "=r"(r[1]), "=r"(r[2]), "=r"(r[3]) : "r"(addr));
}

__device__ __forceinline__ void ldsm4t(unsigned r[4], uint32_t addr) {
  asm volatile("ldmatrix.sync.aligned.m8n8.x4.trans.shared.b16 {%0,%1,%2,%3}, [%4];"
               : "=r"(r[0]), "=r"(r[1]), "=r"(r[2]), "=r"(r[3]) : "r"(addr));
}

__device__ __forceinline__ void mma_f16(float d[4], const unsigned a[4],
                                        unsigned b0, unsigned b1) {
  asm volatile(
      "mma.sync.aligned.m16n8k16.row.col.f32.f16.f16.f32 "
      "{%0,%1,%2,%3}, {%4,%5,%6,%7}, {%8,%9}, {%0,%1,%2,%3};"
      : "+f"(d[0]), "+f"(d[1]), "+f"(d[2]), "+f"(d[3])
      : "r"(a[0]), "r"(a[1]), "r"(a[2]), "r"(a[3]), "r"(b0), "r"(b1));
}

__device__ __forceinline__ void split_store(__half* H, __half* L, size_t idx,
                                            float v) {
  __half h = __float2half_rn(v);
  H[idx] = h;
  L[idx] = __float2half_rn(v - __half2float(h));
}

// ---------------------------------------------------------------------------
// Prep kernels
// ---------------------------------------------------------------------------
// fp32 -> fp16 hi/lo (activations for GEMM)
__global__ void split_h(const float4* __restrict__ X, uint2* __restrict__ Xh,
                        uint2* __restrict__ Xl, int n4) {
  int i = blockIdx.x * 256 + threadIdx.x;
  if (i >= n4) return;
  float4 v = X[i];
  float hx = __half2float(__float2half_rn(v.x));
  float hy = __half2float(__float2half_rn(v.y));
  float hz = __half2float(__float2half_rn(v.z));
  float hw = __half2float(__float2half_rn(v.w));
  __half2 h0 = __floats2half2_rn(hx, hy), h1 = __floats2half2_rn(hz, hw);
  __half2 l0 = __floats2half2_rn(v.x - hx, v.y - hy);
  __half2 l1 = __floats2half2_rn(v.z - hz, v.w - hw);
  uint2 ho, lo;
  ho.x = *(unsigned*)&h0; ho.y = *(unsigned*)&h1;
  lo.x = *(unsigned*)&l0; lo.y = *(unsigned*)&l1;
  Xh[i] = ho;
  Xl[i] = lo;
}

// W [K,N] fp32 row-major -> Wh [N,K] fp16 row-major
__global__ void transpose_h(const float* __restrict__ W, __half* __restrict__ Wh,
                            int K, int N) {
  __shared__ float t[32][33];
  const int n0 = blockIdx.x << 5, k0 = blockIdx.y << 5;
  const int tx = threadIdx.x, ty = threadIdx.y;  // 32 x 8
#pragma unroll
  for (int i = 0; i < 32; i += 8)
    t[ty + i][tx] = W[(size_t)(k0 + ty + i) * N + n0 + tx];
  __syncthreads();
#pragma unroll
  for (int i = 0; i < 32; i += 8)
    Wh[(size_t)(n0 + ty + i) * K + k0 + tx] = __float2half_rn(t[tx][ty + i]);
}

// Fused RoPE + fp16 hi/lo conversion: g_qkv -> Q(scaled)/K/V arrays
__global__ void rope_convert(const float* __restrict__ qkv,
                             const int* __restrict__ positions) {
  const int t = blockIdx.x;
  const int tid = threadIdx.x;  // 256
  const float pos = (float)positions[t];
  const float* row = qkv + (size_t)t * QKV_N;

  // Q: 32 heads x 64 pairs, scaled by ATTN_SCALE
  for (int i = tid; i < 2048; i += 256) {
    int head = i >> 6, d = i & 63;
    float inv = expf(-((float)d * (1.0f / 64.0f)) * 13.815510557964274f);
    float fr = pos * inv;
    float c = cosf(fr), s = sinf(fr);
    float x1 = row[head * 128 + d], x2 = row[head * 128 + d + 64];
    size_t o = (size_t)t * 4096 + head * 128 + d;
    split_store(g_qh, g_ql, o,      (x1 * c - x2 * s) * ATTN_SCALE);
    split_store(g_qh, g_ql, o + 64, (x2 * c + x1 * s) * ATTN_SCALE);
  }
  // K: 8 heads x 64 pairs
  for (int i = tid; i < 512; i += 256) {
    int head = i >> 6, d = i & 63;
    float inv = expf(-((float)d * (1.0f / 64.0f)) * 13.815510557964274f);
    float fr = pos * inv;
    float c = cosf(fr), s = sinf(fr);
    float x1 = row[4096 + head * 128 + d], x2 = row[4096 + head * 128 + d + 64];
    size_t o = (size_t)t * 1024 + head * 128 + d;
    split_store(g_kh, g_kl, o,      x1 * c - x2 * s);
    split_store(g_kh, g_kl, o + 64, x2 * c + x1 * s);
  }
  // V: 1024 values
  for (int i = tid; i < 1024; i += 256)
    split_store(g_vh, g_vl, (size_t)t * 1024 + i, row[5120 + i]);
}

// ---------------------------------------------------------------------------
// 2-term fp16 GEMM: C = (Ah+Al) @ fp16(B)^T. A hi/lo [M,K], B [N,K] fp16.
// BM=BN=128, BK=32, 3-stage cp.async, 2 CTAs/SM, 8 warps, warp tile 32x64.
// smem tile 128x64B, swizzle seg^((row>>1)&3)
// ---------------------------------------------------------------------------
__global__ __launch_bounds__(256, 2) void gemm_h2(
    const __half* __restrict__ pAh, const __half* __restrict__ pAl,
    const __half* __restrict__ pBh, float* __restrict__ C, int N, int K) {
  const uint32_t smb = smem_u32(dyn_smem);

  const int tid  = threadIdx.x;
  const int lane = tid & 31;
  const int warp = tid >> 5;
  const int wm = warp & 3;
  const int wn = warp >> 2;
  const int bm = blockIdx.y * 128;
  const int bn = blockIdx.x * 128;

  const __half* aH = pAh + (size_t)bm * K;
  const __half* aL = pAl + (size_t)bm * K;
  const __half* bH = pBh + (size_t)bn * K;

  const int crow = tid >> 1;
  const int cs0  = (tid & 1) << 1;
  const int csw  = (crow >> 1) & 3;
  const uint32_t cd0 = (uint32_t)(crow * 64 + ((cs0 ^ csw) << 4));
  const uint32_t cd1 = (uint32_t)(crow * 64 + (((cs0 + 1) ^ csw) << 4));
  const int cse = cs0 << 3;

  const int rowA = wm * 32 + (lane & 7) + ((lane >> 3) & 1) * 8;
  const int hcA  = (lane >> 4) & 1;
  const int swA  = (rowA >> 1) & 3;
  const uint32_t aofs = (uint32_t)(rowA * 64);
  const uint32_t xsa0 = (uint32_t)(((0 * 2 + hcA) ^ swA) << 4);
  const uint32_t xsa1 = (uint32_t)(((1 * 2 + hcA) ^ swA) << 4);

  const int rowB = wn * 64 + (lane & 7) + ((lane >> 4) & 1) * 8;
  const int hcB  = (lane >> 3) & 1;
  const int swB  = (rowB >> 1) & 3;
  const uint32_t bofs = (uint32_t)(rowB * 64);
  const uint32_t xsb0 = (uint32_t)(((0 * 2 + hcB) ^ swB) << 4);
  const uint32_t xsb1 = (uint32_t)(((1 * 2 + hcB) ^ swB) << 4);

  float acc[2][8][4];
#pragma unroll
  for (int i = 0; i < 2; i++)
#pragma unroll
    for (int j = 0; j < 8; j++)
#pragma unroll
      for (int r = 0; r < 4; r++) acc[i][j][r] = 0.f;

  const int NC = K >> 5;

#define ISSUE(c)                                                              \
  do {                                                                        \
    uint32_t sb = smb + (uint32_t)((c) % 3) * STG_BYTES;                      \
    size_t gg = (size_t)crow * K + ((c) << 5) + cse;                          \
    cp16(sb + cd0,              aH + gg); cp16(sb + cd1,              aH + gg + 8); \
    cp16(sb + TILE_B + cd0,     aL + gg); cp16(sb + TILE_B + cd1,     aL + gg + 8); \
    cp16(sb + 2 * TILE_B + cd0, bH + gg); cp16(sb + 2 * TILE_B + cd1, bH + gg + 8); \
    asm volatile("cp.async.commit_group;" ::: "memory");                      \
  } while (0)

  ISSUE(0);
  ISSUE(1);

  for (int c = 0; c < NC; ++c) {
    asm volatile("cp.async.wait_group 1;" ::: "memory");
    __syncthreads();
    if (c + 2 < NC) ISSUE(c + 2);

    const uint32_t sb  = smb + (uint32_t)(c % 3) * STG_BYTES;
    const uint32_t abh = sb + aofs;
    const uint32_t abl = abh + TILE_B;
    const uint32_t bbh = sb + 2 * TILE_B + bofs;

#pragma unroll
    for (int st = 0; st < 2; ++st) {
      const uint32_t xa = st ? xsa1 : xsa0;
      const uint32_t xb = st ? xsb1 : xsb0;
      unsigned ah[2][4], al[2][4];
      ldsm4(ah[0], abh + xa);
      ldsm4(ah[1], abh + 1024 + xa);
      ldsm4(al[0], abl + xa);
      ldsm4(al[1], abl + 1024 + xa);
#pragma unroll
      for (int p = 0; p < 4; ++p) {
        unsigned bh[4];
        ldsm4(bh, bbh + p * 1024 + xb);
#pragma unroll
        for (int mi = 0; mi < 2; ++mi)
#pragma unroll
          for (int sub = 0; sub < 2; ++sub) {
            const int ni = p * 2 + sub;
            mma_f16(acc[mi][ni], ah[mi], bh[sub * 2], bh[sub * 2 + 1]);
            mma_f16(acc[mi][ni], al[mi], bh[sub * 2], bh[sub * 2 + 1]);
          }
      }
    }
  }
#undef ISSUE

  const int g  = lane >> 2;
  const int tg = lane & 3;
#pragma unroll
  for (int mi = 0; mi < 2; mi++) {
    int r0 = bm + wm * 32 + mi * 16 + g;
#pragma unroll
    for (int ni = 0; ni < 8; ni++) {
      int c = bn + wn * 64 + ni * 8 + tg * 2;
      C[(size_t)r0 * N + c]           = acc[mi][ni][0];
      C[(size_t)r0 * N + c + 1]       = acc[mi][ni][1];
      C[(size_t)(r0 + 8) * N + c]     = acc[mi][ni][2];
      C[(size_t)(r0 + 8) * N + c + 1] = acc[mi][ni][3];
    }
  }
}

// ---------------------------------------------------------------------------
// Flash attention v2: fp16 + ldmatrix + cp.async, 2 CTAs/SM.
// CTA = (head, 64-row q tile), 128 threads, 4 warps (16 q rows each).
// S = Qs K^T 3-term fp16; PV: P fp16 x (Vh + Vl) 2-term.
// Tiles 64x128 fp16, 256B rows, swizzle seg^(row&7). P 64x64 fp16 128B rows.
// Writes output as fp16 hi/lo directly (feeds Wo GEMM).
// ---------------------------------------------------------------------------
__global__ __launch_bounds__(128) void attn2(__half* __restrict__ oh,
                                             __half* __restrict__ ol) {
  char* smc = dyn_smem;
  const uint32_t smb = smem_u32(smc);
  const uint32_t oQh = 0, oQl = 16384, oKh = 32768, oKl = 49152;
  const uint32_t oVh = 65536, oVl = 81920, oPs = 98304;

  const int h = blockIdx.x, qt = blockIdx.y;
  const int kvh = h >> 2;
  const int q0 = qt * 64;
  const int tid = threadIdx.x, lane = tid & 31, w = tid >> 5;
  const int g = lane >> 2, tg = lane & 3;

  // Q tile load (once)
  {
    const int row = tid >> 1, s0 = (tid & 1) * 8, rx = row & 7;
    const size_t gq = (size_t)(q0 + row) * 4096 + h * 128 + s0 * 8;
    const uint32_t dr = smb + row * 256;
#pragma unroll
    for (int s = 0; s < 8; ++s) {
      uint32_t d = dr + (((s0 + s) ^ rx) << 4);
      cp16(oQh + d, g_qh + gq + s * 8);
      cp16(oQl + d, g_ql + gq + s * 8);
    }
    asm volatile("cp.async.commit_group;" ::: "memory");
  }

  // fragment geometry
  const int rowA = w * 16 + (lane & 7) + ((lane >> 3) & 1) * 8;
  const int rxA = lane & 7;           // rowA & 7
  const int hcA = (lane >> 4) & 1;
  const uint32_t aQ = smb + (uint32_t)rowA * 256;
  const uint32_t aP = smb + oPs + (uint32_t)rowA * 128;
  const int rBb = (lane & 7) + ((lane >> 4) & 1) * 8;
  const int hcB = (lane >> 3) & 1;
  const int subm = lane >> 3;
  const int rV = (lane & 7) + ((subm & 1) << 3);
  const int hsV = subm >> 1;

  float m0 = -1e30f, m1 = -1e30f, l0 = 0.f, l1 = 0.f;
  float O[16][4];
#pragma unroll
  for (int i = 0; i < 16; i++)
#pragma unroll
    for (int r = 0; r < 4; r++) O[i][r] = 0.f;

  const int kvrow = tid >> 1, kvs0 = (tid & 1) * 8, kvrx = kvrow & 7;
  const uint32_t kvdr = smb + kvrow * 256;

  for (int j = 0; j <= qt; ++j) {
    __syncthreads();  // all warps done reading K/V of previous tile
    {
      const size_t gk = (size_t)(j * 64 + kvrow) * 1024 + kvh * 128 + kvs0 * 8;
#pragma unroll
      for (int s = 0; s < 8; ++s) {
        uint32_t d = kvdr + (((kvs0 + s) ^ kvrx) << 4);
        cp16(oKh + d, g_kh + gk + s * 8);
        cp16(oKl + d, g_kl + gk + s * 8);
        cp16(oVh + d, g_vh + gk + s * 8);
        cp16(oVl + d, g_vl + gk + s * 8);
      }
    }
    asm volatile("cp.async.commit_group;" ::: "memory");
    asm volatile("cp.async.wait_group 0;" ::: "memory");
    __syncthreads();

    // ---- S = Qs K^T (warp: 16 q rows x 64 kv), 3-term fp16 ----
    float s[8][4];
#pragma unroll
    for (int ni = 0; ni < 8; ni++)
#pragma unroll
      for (int r = 0; r < 4; r++) s[ni][r] = 0.f;

#pragma unroll
    for (int kst = 0; kst < 8; ++kst) {
      unsigned qh[4], ql[4];
      const uint32_t xa = (uint32_t)(((kst * 2 + hcA) ^ rxA) << 4);
      ldsm4(qh, aQ + oQh + xa);
      ldsm4(ql, aQ + oQl + xa);
#pragma unroll
      for (int p = 0; p < 4; ++p) {
        const int rb = p * 16 + rBb;
        const uint32_t ab =
            smb + (uint32_t)rb * 256 + (uint32_t)(((kst * 2 + hcB) ^ (rb & 7)) << 4);
        unsigned kh[4], kl[4];
        ldsm4(kh, ab + oKh);
        ldsm4(kl, ab + oKl);
#pragma unroll
        for (int sub = 0; sub < 2; ++sub) {
          const int ni = p * 2 + sub;
          mma_f16(s[ni], qh, kh[sub * 2], kh[sub * 2 + 1]);
          mma_f16(s[ni], ql, kh[sub * 2], kh[sub * 2 + 1]);
          mma_f16(s[ni], qh, kl[sub * 2], kl[sub * 2 + 1]);
        }
      }
    }

    // ---- online softmax (scale pre-folded into Q) ----
    const int gr0 = q0 + w * 16 + g;
    const int gr1 = gr0 + 8;
    float tm0 = -1e30f, tm1 = -1e30f;
#pragma unroll
    for (int ni = 0; ni < 8; ni++) {
#pragma unroll
      for (int cc = 0; cc < 2; cc++) {
        int gc = j * 64 + ni * 8 + tg * 2 + cc;
        float v0 = s[ni][cc];
        float v1 = s[ni][2 + cc];
        if (gc > gr0) v0 = -1e30f;
        if (gc > gr1) v1 = -1e30f;
        s[ni][cc] = v0;
        s[ni][2 + cc] = v1;
        tm0 = fmaxf(tm0, v0);
        tm1 = fmaxf(tm1, v1);
      }
    }
    tm0 = fmaxf(tm0, __shfl_xor_sync(0xffffffffu, tm0, 1));
    tm0 = fmaxf(tm0, __shfl_xor_sync(0xffffffffu, tm0, 2));
    tm1 = fmaxf(tm1, __shfl_xor_sync(0xffffffffu, tm1, 1));
    tm1 = fmaxf(tm1, __shfl_xor_sync(0xffffffffu, tm1, 2));

    float nm0 = fmaxf(m0, tm0), nm1 = fmaxf(m1, tm1);
    float a0 = __expf(m0 - nm0), a1 = __expf(m1 - nm1);

    const uint32_t pr0 = oPs + (uint32_t)(w * 16 + g) * 128;
    const uint32_t pr1 = pr0 + 1024;
    float ps0 = 0.f, ps1 = 0.f;
#pragma unroll
    for (int ni = 0; ni < 8; ni++) {
      float p00 = __expf(s[ni][0] - nm0);
      float p01 = __expf(s[ni][1] - nm0);
      float p10 = __expf(s[ni][2] - nm1);
      float p11 = __expf(s[ni][3] - nm1);
      ps0 += p00 + p01;
      ps1 += p10 + p11;
      const uint32_t px = (uint32_t)(((ni ^ g) << 4) + tg * 4);
      *reinterpret_cast<__half2*>(smc + pr0 + px) = __floats2half2_rn(p00, p01);
      *reinterpret_cast<__half2*>(smc + pr1 + px) = __floats2half2_rn(p10, p11);
    }
    ps0 += __shfl_xor_sync(0xffffffffu, ps0, 1);
    ps0 += __shfl_xor_sync(0xffffffffu, ps0, 2);
    ps1 += __shfl_xor_sync(0xffffffffu, ps1, 1);
    ps1 += __shfl_xor_sync(0xffffffffu, ps1, 2);

    l0 = l0 * a0 + ps0;
    l1 = l1 * a1 + ps1;
    m0 = nm0;
    m1 = nm1;
#pragma unroll
    for (int ni = 0; ni < 16; ni++) {
      O[ni][0] *= a0; O[ni][1] *= a0;
      O[ni][2] *= a1; O[ni][3] *= a1;
    }
    __syncwarp();

    // ---- O += P (Vh + Vl) ----
#pragma unroll
    for (int k2 = 0; k2 < 4; ++k2) {
      unsigned pf[4];
      ldsm4(pf, aP + (uint32_t)(((k2 * 2 + hcA) ^ rxA) << 4));
      const int rv = k2 * 16 + rV;
      const uint32_t vb = smb + (uint32_t)rv * 256;
      const int rxv = rv & 7;
#pragma unroll
      for (int dg = 0; dg < 8; ++dg) {
        unsigned vh[4], vl[4];
        const uint32_t xs = (uint32_t)(((dg * 2 + hsV) ^ rxv) << 4);
        ldsm4t(vh, vb + oVh + xs);
        ldsm4t(vl, vb + oVl + xs);
#pragma unroll
        for (int sub = 0; sub < 2; ++sub) {
          const int ni = dg * 2 + sub;
          mma_f16(O[ni], pf, vh[sub * 2], vh[sub * 2 + 1]);
          mma_f16(O[ni], pf, vl[sub * 2], vl[sub * 2 + 1]);
        }
      }
    }
  }

  // epilogue -> fp16 hi/lo for the Wo GEMM
  const float inv0 = 1.f / l0;
  const float inv1 = 1.f / l1;
  const int r0 = q0 + w * 16 + g;
#pragma unroll
  for (int ni = 0; ni < 16; ni++) {
    const int c = h * HD + ni * 8 + tg * 2;
    const size_t i0 = (size_t)r0 * HID + c;
    const size_t i1 = (size_t)(r0 + 8) * HID + c;
    split_store(oh, ol, i0,     O[ni][0] * inv0);
    split_store(oh, ol, i0 + 1, O[ni][1] * inv0);
    split_store(oh, ol, i1,     O[ni][2] * inv1);
    split_store(oh, ol, i1 + 1, O[ni][3] * inv1);
  }
}

// ---------------------------------------------------------------------------
// launch
// ---------------------------------------------------------------------------
extern "C" void kernel_launch(void* const* d_in, const int* in_sizes, int n_in,
                              void* d_out, int out_size) {
  (void)in_sizes; (void)n_in; (void)out_size;
  const int*   positions = (const int*)d_in[0];
  const float* hidden    = (const float*)d_in[1];
  const float* Wqkv      = (const float*)d_in[2];
  const float* Wo        = (const float*)d_in[3];
  float* out = (float*)d_out;

  float* qkv_p;
  __half *ah, *al, *wqh, *woh;
  cudaGetSymbolAddress((void**)&qkv_p, g_qkv);
  cudaGetSymbolAddress((void**)&ah, g_ah);
  cudaGetSymbolAddress((void**)&al, g_al);
  cudaGetSymbolAddress((void**)&wqh, g_wqh);
  cudaGetSymbolAddress((void**)&woh, g_woh);

  cudaFuncSetAttribute(gemm_h2, cudaFuncAttributeMaxDynamicSharedMemorySize,
                       GEMM_SMEM);
  cudaFuncSetAttribute(attn2, cudaFuncAttributeMaxDynamicSharedMemorySize,
                       ATTN_SMEM);

  // Prep
  transpose_h<<<dim3(QKV_N / 32, HID / 32), dim3(32, 8)>>>(Wqkv, wqh, HID, QKV_N);
  transpose_h<<<dim3(HID / 32, HID / 32), dim3(32, 8)>>>(Wo, woh, HID, HID);
  split_h<<<(T_SEQ * HID / 4 + 255) / 256, 256>>>(
      (const float4*)hidden, (uint2*)ah, (uint2*)al, T_SEQ * HID / 4);

  // 1) QKV projection
  gemm_h2<<<dim3(QKV_N / 128, T_SEQ / 128), 256, GEMM_SMEM>>>(
      ah, al, wqh, qkv_p, QKV_N, HID);
  // 2) RoPE + fp16 conversion
  rope_convert<<<T_SEQ, 256>>>(qkv_p, positions);
  // 3) Flash attention (writes fp16 hi/lo into g_ah/g_al)
  attn2<<<dim3(NHEADS, T_SEQ / 64), 128, ATTN_SMEM>>>(ah, al);
  // 4) Output projection
  gemm_h2<<<dim3(HID / 128, T_SEQ / 128), 256, GEMM_SMEM>>>(
      ah, al, woh, out, HID, HID);
}

// round 8
// speedup vs baseline: 1.5891x; 1.5891x over previous
#include <cuda_runtime.h>
#include <cuda_fp16.h>
#include <cstdint>

#define T_SEQ 2048
#define HID   4096
#define QKV_N 6144
#define HD    128
#define NHEADS 32
#define ATTN_SCALE 0.08838834764831845f   // 128^-0.5

// GEMM: BM=BN=128, BK=32 (fp16), 3 tiles/stage (Ah,Al,Bh), 4 stages, 2 CTAs/SM
#define TILE_B 8192
#define STG_BYTES (3 * TILE_B)
#define GEMM_SMEM (4 * STG_BYTES)

// Attention: Qh,Ql,Kh,Kl,Vh,Vl 64x128 fp16 (16KB each) + P 64x64 fp16 (8KB)
#define ATTN_SMEM (6 * 16384 + 8192)

extern __shared__ char dyn_smem[];

// ---------------------------------------------------------------------------
// Scratch (allocation-free rule: __device__ globals)
// ---------------------------------------------------------------------------
__device__ float g_qkv[(size_t)T_SEQ * QKV_N];
__device__ __align__(16) __half g_ah[(size_t)T_SEQ * HID];    // GEMM A hi
__device__ __align__(16) __half g_al[(size_t)T_SEQ * HID];    // GEMM A lo
__device__ __align__(16) __half g_wqh[(size_t)QKV_N * HID];   // Wqkv^T fp16 [N,K]
__device__ __align__(16) __half g_woh[(size_t)HID * HID];     // Wo^T fp16
__device__ __align__(16) __half g_qh[(size_t)T_SEQ * HID];    // roped+scaled Q hi
__device__ __align__(16) __half g_ql[(size_t)T_SEQ * HID];
__device__ __align__(16) __half g_kh[(size_t)T_SEQ * 1024];   // roped K hi
__device__ __align__(16) __half g_kl[(size_t)T_SEQ * 1024];
__device__ __align__(16) __half g_vh[(size_t)T_SEQ * 1024];   // V hi
__device__ __align__(16) __half g_vl[(size_t)T_SEQ * 1024];

// ---------------------------------------------------------------------------
// helpers
// ---------------------------------------------------------------------------
__device__ __forceinline__ uint32_t smem_u32(const void* p) {
  uint32_t a;
  asm("{ .reg .u64 t; cvta.to.shared.u64 t, %1; cvt.u32.u64 %0, t; }"
      : "=r"(a) : "l"(p));
  return a;
}

__device__ __forceinline__ void cp16(uint32_t dst, const void* src) {
  asm volatile("cp.async.cg.shared.global [%0], [%1], 16;"
               :: "r"(dst), "l"(src) : "memory");
}

__device__ __forceinline__ void ldsm4(unsigned r[4], uint32_t addr) {
  asm volatile("ldmatrix.sync.aligned.m8n8.x4.shared.b16 {%0,%1,%2,%3}, [%4];"
               : "=r"(r[0]), "=r"(r[1]), "=r"(r[2]), "=r"(r[3]) : "r"(addr));
}

__device__ __forceinline__ void ldsm4t(unsigned r[4], uint32_t addr) {
  asm volatile("ldmatrix.sync.aligned.m8n8.x4.trans.shared.b16 {%0,%1,%2,%3}, [%4];"
               : "=r"(r[0]), "=r"(r[1]), "=r"(r[2]), "=r"(r[3]) : "r"(addr));
}

__device__ __forceinline__ void mma_f16(float d[4], const unsigned a[4],
                                        unsigned b0, unsigned b1) {
  asm volatile(
      "mma.sync.aligned.m16n8k16.row.col.f32.f16.f16.f32 "
      "{%0,%1,%2,%3}, {%4,%5,%6,%7}, {%8,%9}, {%0,%1,%2,%3};"
      : "+f"(d[0]), "+f"(d[1]), "+f"(d[2]), "+f"(d[3])
      : "r"(a[0]), "r"(a[1]), "r"(a[2]), "r"(a[3]), "r"(b0), "r"(b1));
}

__device__ __forceinline__ void split_store(__half* H, __half* L, size_t idx,
                                            float v) {
  __half h = __float2half_rn(v);
  H[idx] = h;
  L[idx] = __float2half_rn(v - __half2float(h));
}

// ---------------------------------------------------------------------------
// Prep kernels
// ---------------------------------------------------------------------------
__global__ void split_h(const float4* __restrict__ X, uint2* __restrict__ Xh,
                        uint2* __restrict__ Xl, int n4) {
  int i = blockIdx.x * 256 + threadIdx.x;
  if (i >= n4) return;
  float4 v = X[i];
  float hx = __half2float(__float2half_rn(v.x));
  float hy = __half2float(__float2half_rn(v.y));
  float hz = __half2float(__float2half_rn(v.z));
  float hw = __half2float(__float2half_rn(v.w));
  __half2 h0 = __floats2half2_rn(hx, hy), h1 = __floats2half2_rn(hz, hw);
  __half2 l0 = __floats2half2_rn(v.x - hx, v.y - hy);
  __half2 l1 = __floats2half2_rn(v.z - hz, v.w - hw);
  uint2 ho, lo;
  ho.x = *(unsigned*)&h0; ho.y = *(unsigned*)&h1;
  lo.x = *(unsigned*)&l0; lo.y = *(unsigned*)&l1;
  Xh[i] = ho;
  Xl[i] = lo;
}

__global__ void transpose_h(const float* __restrict__ W, __half* __restrict__ Wh,
                            int K, int N) {
  __shared__ float t[32][33];
  const int n0 = blockIdx.x << 5, k0 = blockIdx.y << 5;
  const int tx = threadIdx.x, ty = threadIdx.y;  // 32 x 8
#pragma unroll
  for (int i = 0; i < 32; i += 8)
    t[ty + i][tx] = W[(size_t)(k0 + ty + i) * N + n0 + tx];
  __syncthreads();
#pragma unroll
  for (int i = 0; i < 32; i += 8)
    Wh[(size_t)(n0 + ty + i) * K + k0 + tx] = __float2half_rn(t[tx][ty + i]);
}

// Fused RoPE + fp16 hi/lo conversion
__global__ void rope_convert(const float* __restrict__ qkv,
                             const int* __restrict__ positions) {
  const int t = blockIdx.x;
  const int tid = threadIdx.x;  // 256
  const float pos = (float)positions[t];
  const float* row = qkv + (size_t)t * QKV_N;

  for (int i = tid; i < 2048; i += 256) {
    int head = i >> 6, d = i & 63;
    float inv = expf(-((float)d * (1.0f / 64.0f)) * 13.815510557964274f);
    float fr = pos * inv;
    float c = cosf(fr), s = sinf(fr);
    float x1 = row[head * 128 + d], x2 = row[head * 128 + d + 64];
    size_t o = (size_t)t * 4096 + head * 128 + d;
    split_store(g_qh, g_ql, o,      (x1 * c - x2 * s) * ATTN_SCALE);
    split_store(g_qh, g_ql, o + 64, (x2 * c + x1 * s) * ATTN_SCALE);
  }
  for (int i = tid; i < 512; i += 256) {
    int head = i >> 6, d = i & 63;
    float inv = expf(-((float)d * (1.0f / 64.0f)) * 13.815510557964274f);
    float fr = pos * inv;
    float c = cosf(fr), s = sinf(fr);
    float x1 = row[4096 + head * 128 + d], x2 = row[4096 + head * 128 + d + 64];
    size_t o = (size_t)t * 1024 + head * 128 + d;
    split_store(g_kh, g_kl, o,      x1 * c - x2 * s);
    split_store(g_kh, g_kl, o + 64, x2 * c + x1 * s);
  }
  for (int i = tid; i < 1024; i += 256)
    split_store(g_vh, g_vl, (size_t)t * 1024 + i, row[5120 + i]);
}

// ---------------------------------------------------------------------------
// 2-term fp16 GEMM, two-pass MMA schedule (no same-acc back-to-back MMAs).
// BM=BN=128, BK=32, 4-stage cp.async, 2 CTAs/SM, 8 warps, warp tile 32x64.
// ---------------------------------------------------------------------------
__global__ __launch_bounds__(256, 2) void gemm_h2(
    const __half* __restrict__ pAh, const __half* __restrict__ pAl,
    const __half* __restrict__ pBh, float* __restrict__ C, int N, int K) {
  const uint32_t smb = smem_u32(dyn_smem);

  const int tid  = threadIdx.x;
  const int lane = tid & 31;
  const int warp = tid >> 5;
  const int wm = warp & 3;
  const int wn = warp >> 2;
  const int bm = blockIdx.y * 128;
  const int bn = blockIdx.x * 128;

  const __half* aH = pAh + (size_t)bm * K;
  const __half* aL = pAl + (size_t)bm * K;
  const __half* bH = pBh + (size_t)bn * K;

  const int crow = tid >> 1;
  const int cs0  = (tid & 1) << 1;
  const int csw  = (crow >> 1) & 3;
  const uint32_t cd0 = (uint32_t)(crow * 64 + ((cs0 ^ csw) << 4));
  const uint32_t cd1 = (uint32_t)(crow * 64 + (((cs0 + 1) ^ csw) << 4));
  const int cse = cs0 << 3;

  const int rowA = wm * 32 + (lane & 7) + ((lane >> 3) & 1) * 8;
  const int hcA  = (lane >> 4) & 1;
  const int swA  = (rowA >> 1) & 3;
  const uint32_t aofs = (uint32_t)(rowA * 64);
  const uint32_t xsa0 = (uint32_t)(((0 * 2 + hcA) ^ swA) << 4);
  const uint32_t xsa1 = (uint32_t)(((1 * 2 + hcA) ^ swA) << 4);

  const int rowB = wn * 64 + (lane & 7) + ((lane >> 4) & 1) * 8;
  const int hcB  = (lane >> 3) & 1;
  const int swB  = (rowB >> 1) & 3;
  const uint32_t bofs = (uint32_t)(rowB * 64);
  const uint32_t xsb0 = (uint32_t)(((0 * 2 + hcB) ^ swB) << 4);
  const uint32_t xsb1 = (uint32_t)(((1 * 2 + hcB) ^ swB) << 4);

  float acc[2][8][4];
#pragma unroll
  for (int i = 0; i < 2; i++)
#pragma unroll
    for (int j = 0; j < 8; j++)
#pragma unroll
      for (int r = 0; r < 4; r++) acc[i][j][r] = 0.f;

  const int NC = K >> 5;

#define ISSUE(c)                                                              \
  do {                                                                        \
    uint32_t sb = smb + (uint32_t)((c) & 3) * STG_BYTES;                      \
    size_t gg = (size_t)crow * K + ((c) << 5) + cse;                          \
    cp16(sb + cd0,              aH + gg); cp16(sb + cd1,              aH + gg + 8); \
    cp16(sb + TILE_B + cd0,     aL + gg); cp16(sb + TILE_B + cd1,     aL + gg + 8); \
    cp16(sb + 2 * TILE_B + cd0, bH + gg); cp16(sb + 2 * TILE_B + cd1, bH + gg + 8); \
    asm volatile("cp.async.commit_group;" ::: "memory");                      \
  } while (0)

  ISSUE(0);
  ISSUE(1);
  ISSUE(2);

  for (int c = 0; c < NC; ++c) {
    asm volatile("cp.async.wait_group 2;" ::: "memory");
    __syncthreads();
    if (c + 3 < NC) ISSUE(c + 3);

    const uint32_t sb  = smb + (uint32_t)(c & 3) * STG_BYTES;
    const uint32_t abh = sb + aofs;
    const uint32_t abl = abh + TILE_B;
    const uint32_t bbh = sb + 2 * TILE_B + bofs;

#pragma unroll
    for (int st = 0; st < 2; ++st) {
      const uint32_t xa = st ? xsa1 : xsa0;
      const uint32_t xb = st ? xsb1 : xsb0;
      unsigned af[2][4], bf[4][4];
      // pass 1: A-hi x B  (16 MMAs, all-distinct accumulators)
      ldsm4(af[0], abh + xa);
      ldsm4(af[1], abh + 1024 + xa);
#pragma unroll
      for (int p = 0; p < 4; ++p) ldsm4(bf[p], bbh + p * 1024 + xb);
#pragma unroll
      for (int p = 0; p < 4; ++p)
#pragma unroll
        for (int mi = 0; mi < 2; ++mi)
#pragma unroll
          for (int sub = 0; sub < 2; ++sub)
            mma_f16(acc[mi][p * 2 + sub], af[mi], bf[p][sub * 2],
                    bf[p][sub * 2 + 1]);
      // pass 2: A-lo x B (reuse af regs; acc distance stays 16)
      ldsm4(af[0], abl + xa);
      ldsm4(af[1], abl + 1024 + xa);
#pragma unroll
      for (int p = 0; p < 4; ++p)
#pragma unroll
        for (int mi = 0; mi < 2; ++mi)
#pragma unroll
          for (int sub = 0; sub < 2; ++sub)
            mma_f16(acc[mi][p * 2 + sub], af[mi], bf[p][sub * 2],
                    bf[p][sub * 2 + 1]);
    }
  }
#undef ISSUE

  const int g  = lane >> 2;
  const int tg = lane & 3;
#pragma unroll
  for (int mi = 0; mi < 2; mi++) {
    int r0 = bm + wm * 32 + mi * 16 + g;
#pragma unroll
    for (int ni = 0; ni < 8; ni++) {
      int c = bn + wn * 64 + ni * 8 + tg * 2;
      C[(size_t)r0 * N + c]           = acc[mi][ni][0];
      C[(size_t)r0 * N + c + 1]       = acc[mi][ni][1];
      C[(size_t)(r0 + 8) * N + c]     = acc[mi][ni][2];
      C[(size_t)(r0 + 8) * N + c + 1] = acc[mi][ni][3];
    }
  }
}

// ---------------------------------------------------------------------------
// Flash attention v2.1: two-pass PV, term-outer S ordering, half2 epilogue.
// ---------------------------------------------------------------------------
__global__ __launch_bounds__(128) void attn2(__half* __restrict__ oh,
                                             __half* __restrict__ ol) {
  char* smc = dyn_smem;
  const uint32_t smb = smem_u32(smc);
  const uint32_t oQh = 0, oQl = 16384, oKh = 32768, oKl = 49152;
  const uint32_t oVh = 65536, oVl = 81920, oPs = 98304;

  const int h = blockIdx.x, qt = blockIdx.y;
  const int kvh = h >> 2;
  const int q0 = qt * 64;
  const int tid = threadIdx.x, lane = tid & 31, w = tid >> 5;
  const int g = lane >> 2, tg = lane & 3;

  // Q tile load (once)
  {
    const int row = tid >> 1, s0 = (tid & 1) * 8, rx = row & 7;
    const size_t gq = (size_t)(q0 + row) * 4096 + h * 128 + s0 * 8;
    const uint32_t dr = smb + row * 256;
#pragma unroll
    for (int s = 0; s < 8; ++s) {
      uint32_t d = dr + (((s0 + s) ^ rx) << 4);
      cp16(oQh + d, g_qh + gq + s * 8);
      cp16(oQl + d, g_ql + gq + s * 8);
    }
    asm volatile("cp.async.commit_group;" ::: "memory");
  }

  const int rowA = w * 16 + (lane & 7) + ((lane >> 3) & 1) * 8;
  const int rxA = lane & 7;
  const int hcA = (lane >> 4) & 1;
  const uint32_t aQ = smb + (uint32_t)rowA * 256;
  const uint32_t aP = smb + oPs + (uint32_t)rowA * 128;
  const int rBb = (lane & 7) + ((lane >> 4) & 1) * 8;
  const int hcB = (lane >> 3) & 1;
  const int subm = lane >> 3;
  const int rV = (lane & 7) + ((subm & 1) << 3);
  const int hsV = subm >> 1;

  float m0 = -1e30f, m1 = -1e30f, l0 = 0.f, l1 = 0.f;
  float O[16][4];
#pragma unroll
  for (int i = 0; i < 16; i++)
#pragma unroll
    for (int r = 0; r < 4; r++) O[i][r] = 0.f;

  const int kvrow = tid >> 1, kvs0 = (tid & 1) * 8, kvrx = kvrow & 7;
  const uint32_t kvdr = smb + kvrow * 256;

  for (int j = 0; j <= qt; ++j) {
    __syncthreads();
    {
      const size_t gk = (size_t)(j * 64 + kvrow) * 1024 + kvh * 128 + kvs0 * 8;
#pragma unroll
      for (int s = 0; s < 8; ++s) {
        uint32_t d = kvdr + (((kvs0 + s) ^ kvrx) << 4);
        cp16(oKh + d, g_kh + gk + s * 8);
        cp16(oKl + d, g_kl + gk + s * 8);
        cp16(oVh + d, g_vh + gk + s * 8);
        cp16(oVl + d, g_vl + gk + s * 8);
      }
    }
    asm volatile("cp.async.commit_group;" ::: "memory");
    asm volatile("cp.async.wait_group 0;" ::: "memory");
    __syncthreads();

    // ---- S = Qs K^T, 3-term fp16, term-outer per p (acc distance 2) ----
    float s[8][4];
#pragma unroll
    for (int ni = 0; ni < 8; ni++)
#pragma unroll
      for (int r = 0; r < 4; r++) s[ni][r] = 0.f;

#pragma unroll
    for (int kst = 0; kst < 8; ++kst) {
      unsigned qh[4], ql[4];
      const uint32_t xa = (uint32_t)(((kst * 2 + hcA) ^ rxA) << 4);
      ldsm4(qh, aQ + oQh + xa);
      ldsm4(ql, aQ + oQl + xa);
#pragma unroll
      for (int p = 0; p < 4; ++p) {
        const int rb = p * 16 + rBb;
        const uint32_t ab =
            smb + (uint32_t)rb * 256 + (uint32_t)(((kst * 2 + hcB) ^ (rb & 7)) << 4);
        unsigned kh[4], kl[4];
        ldsm4(kh, ab + oKh);
        ldsm4(kl, ab + oKl);
        const int n0i = p * 2;
        mma_f16(s[n0i],     qh, kh[0], kh[1]);
        mma_f16(s[n0i + 1], qh, kh[2], kh[3]);
        mma_f16(s[n0i],     ql, kh[0], kh[1]);
        mma_f16(s[n0i + 1], ql, kh[2], kh[3]);
        mma_f16(s[n0i],     qh, kl[0], kl[1]);
        mma_f16(s[n0i + 1], qh, kl[2], kl[3]);
      }
    }

    // ---- online softmax ----
    const int gr0 = q0 + w * 16 + g;
    const int gr1 = gr0 + 8;
    float tm0 = -1e30f, tm1 = -1e30f;
#pragma unroll
    for (int ni = 0; ni < 8; ni++) {
#pragma unroll
      for (int cc = 0; cc < 2; cc++) {
        int gc = j * 64 + ni * 8 + tg * 2 + cc;
        float v0 = s[ni][cc];
        float v1 = s[ni][2 + cc];
        if (gc > gr0) v0 = -1e30f;
        if (gc > gr1) v1 = -1e30f;
        s[ni][cc] = v0;
        s[ni][2 + cc] = v1;
        tm0 = fmaxf(tm0, v0);
        tm1 = fmaxf(tm1, v1);
      }
    }
    tm0 = fmaxf(tm0, __shfl_xor_sync(0xffffffffu, tm0, 1));
    tm0 = fmaxf(tm0, __shfl_xor_sync(0xffffffffu, tm0, 2));
    tm1 = fmaxf(tm1, __shfl_xor_sync(0xffffffffu, tm1, 1));
    tm1 = fmaxf(tm1, __shfl_xor_sync(0xffffffffu, tm1, 2));

    float nm0 = fmaxf(m0, tm0), nm1 = fmaxf(m1, tm1);
    float a0 = __expf(m0 - nm0), a1 = __expf(m1 - nm1);

    const uint32_t pr0 = oPs + (uint32_t)(w * 16 + g) * 128;
    const uint32_t pr1 = pr0 + 1024;
    float ps0 = 0.f, ps1 = 0.f;
#pragma unroll
    for (int ni = 0; ni < 8; ni++) {
      float p00 = __expf(s[ni][0] - nm0);
      float p01 = __expf(s[ni][1] - nm0);
      float p10 = __expf(s[ni][2] - nm1);
      float p11 = __expf(s[ni][3] - nm1);
      ps0 += p00 + p01;
      ps1 += p10 + p11;
      const uint32_t px = (uint32_t)(((ni ^ g) << 4) + tg * 4);
      *reinterpret_cast<__half2*>(smc + pr0 + px) = __floats2half2_rn(p00, p01);
      *reinterpret_cast<__half2*>(smc + pr1 + px) = __floats2half2_rn(p10, p11);
    }
    ps0 += __shfl_xor_sync(0xffffffffu, ps0, 1);
    ps0 += __shfl_xor_sync(0xffffffffu, ps0, 2);
    ps1 += __shfl_xor_sync(0xffffffffu, ps1, 1);
    ps1 += __shfl_xor_sync(0xffffffffu, ps1, 2);

    l0 = l0 * a0 + ps0;
    l1 = l1 * a1 + ps1;
    m0 = nm0;
    m1 = nm1;
#pragma unroll
    for (int ni = 0; ni < 16; ni++) {
      O[ni][0] *= a0; O[ni][1] *= a0;
      O[ni][2] *= a1; O[ni][3] *= a1;
    }
    __syncwarp();

    // ---- O += P (Vh + Vl), two passes: all-hi then all-lo ----
#pragma unroll
    for (int k2 = 0; k2 < 4; ++k2) {
      unsigned pf[4];
      ldsm4(pf, aP + (uint32_t)(((k2 * 2 + hcA) ^ rxA) << 4));
      const int rv = k2 * 16 + rV;
      const uint32_t vb = smb + (uint32_t)rv * 256;
      const int rxv = rv & 7;
      unsigned vf[8][4];
#pragma unroll
      for (int dg = 0; dg < 8; ++dg)
        ldsm4t(vf[dg], vb + oVh + (uint32_t)(((dg * 2 + hsV) ^ rxv) << 4));
#pragma unroll
      for (int dg = 0; dg < 8; ++dg) {
        mma_f16(O[dg * 2],     pf, vf[dg][0], vf[dg][1]);
        mma_f16(O[dg * 2 + 1], pf, vf[dg][2], vf[dg][3]);
      }
#pragma unroll
      for (int dg = 0; dg < 8; ++dg)
        ldsm4t(vf[dg], vb + oVl + (uint32_t)(((dg * 2 + hsV) ^ rxv) << 4));
#pragma unroll
      for (int dg = 0; dg < 8; ++dg) {
        mma_f16(O[dg * 2],     pf, vf[dg][0], vf[dg][1]);
        mma_f16(O[dg * 2 + 1], pf, vf[dg][2], vf[dg][3]);
      }
    }
  }

  // epilogue -> fp16 hi/lo, half2 paired stores
  const float inv0 = 1.f / l0;
  const float inv1 = 1.f / l1;
  const int r0 = q0 + w * 16 + g;
#pragma unroll
  for (int ni = 0; ni < 16; ni++) {
    const int c = h * HD + ni * 8 + tg * 2;
    const size_t i0 = (size_t)r0 * HID + c;
    const size_t i1 = (size_t)(r0 + 8) * HID + c;
    float v00 = O[ni][0] * inv0, v01 = O[ni][1] * inv0;
    float v10 = O[ni][2] * inv1, v11 = O[ni][3] * inv1;
    __half2 h0 = __floats2half2_rn(v00, v01);
    __half2 h1 = __floats2half2_rn(v10, v11);
    *reinterpret_cast<__half2*>(oh + i0) = h0;
    *reinterpret_cast<__half2*>(oh + i1) = h1;
    *reinterpret_cast<__half2*>(ol + i0) =
        __floats2half2_rn(v00 - __half2float(__low2half(h0)),
                          v01 - __half2float(__high2half(h0)));
    *reinterpret_cast<__half2*>(ol + i1) =
        __floats2half2_rn(v10 - __half2float(__low2half(h1)),
                          v11 - __half2float(__high2half(h1)));
  }
}

// ---------------------------------------------------------------------------
// launch
// ---------------------------------------------------------------------------
extern "C" void kernel_launch(void* const* d_in, const int* in_sizes, int n_in,
                              void* d_out, int out_size) {
  (void)in_sizes; (void)n_in; (void)out_size;
  const int*   positions = (const int*)d_in[0];
  const float* hidden    = (const float*)d_in[1];
  const float* Wqkv      = (const float*)d_in[2];
  const float* Wo        = (const float*)d_in[3];
  float* out = (float*)d_out;

  float* qkv_p;
  __half *ah, *al, *wqh, *woh;
  cudaGetSymbolAddress((void**)&qkv_p, g_qkv);
  cudaGetSymbolAddress((void**)&ah, g_ah);
  cudaGetSymbolAddress((void**)&al, g_al);
  cudaGetSymbolAddress((void**)&wqh, g_wqh);
  cudaGetSymbolAddress((void**)&woh, g_woh);

  cudaFuncSetAttribute(gemm_h2, cudaFuncAttributeMaxDynamicSharedMemorySize,
                       GEMM_SMEM);
  cudaFuncSetAttribute(attn2, cudaFuncAttributeMaxDynamicSharedMemorySize,
                       ATTN_SMEM);

  // Prep
  transpose_h<<<dim3(QKV_N / 32, HID / 32), dim3(32, 8)>>>(Wqkv, wqh, HID, QKV_N);
  transpose_h<<<dim3(HID / 32, HID / 32), dim3(32, 8)>>>(Wo, woh, HID, HID);
  split_h<<<(T_SEQ * HID / 4 + 255) / 256, 256>>>(
      (const float4*)hidden, (uint2*)ah, (uint2*)al, T_SEQ * HID / 4);

  // 1) QKV projection
  gemm_h2<<<dim3(QKV_N / 128, T_SEQ / 128), 256, GEMM_SMEM>>>(
      ah, al, wqh, qkv_p, QKV_N, HID);
  // 2) RoPE + fp16 conversion
  rope_convert<<<T_SEQ, 256>>>(qkv_p, positions);
  // 3) Flash attention (writes fp16 hi/lo into g_ah/g_al)
  attn2<<<dim3(NHEADS, T_SEQ / 64), 128, ATTN_SMEM>>>(ah, al);
  // 4) Output projection
  gemm_h2<<<dim3(HID / 128, T_SEQ / 128), 256, GEMM_SMEM>>>(
      ah, al, woh, out, HID, HID);
}

// round 9
// speedup vs baseline: 1.7916x; 1.1274x over previous
#include <cuda_runtime.h>
#include <cuda_fp16.h>
#include <cstdint>

#define T_SEQ 2048
#define HID   4096
#define QKV_N 6144
#define HD    128
#define NHEADS 32
#define ATTN_SCALE 0.08838834764831845f   // 128^-0.5

// GEMM: BM=BN=128, BK=32 (fp16), 3 tiles/stage (Ah,Al,Bh), 4 stages, 2 CTAs/SM
#define TILE_B 8192
#define STG_BYTES (3 * TILE_B)
#define GEMM_SMEM (4 * STG_BYTES)

// Attention v3: Q 128x128 hi/lo (64KB) + 2-stage KV (2x64KB) + P 128x64 (16KB)
#define AQH 0
#define AQL 32768
#define AKV 65536          // stage s at AKV + s*65536: Kh,Kl,Vh,Vl 16KB each
#define APS (AKV + 2 * 65536)
#define ATTN_SMEM (APS + 16384)   // 212992

extern __shared__ char dyn_smem[];

// ---------------------------------------------------------------------------
// Scratch (allocation-free rule: __device__ globals)
// ---------------------------------------------------------------------------
__device__ float g_qkv[(size_t)T_SEQ * QKV_N];
__device__ __align__(16) __half g_ah[(size_t)T_SEQ * HID];    // GEMM A hi
__device__ __align__(16) __half g_al[(size_t)T_SEQ * HID];    // GEMM A lo
__device__ __align__(16) __half g_wqh[(size_t)QKV_N * HID];   // Wqkv^T fp16 [N,K]
__device__ __align__(16) __half g_woh[(size_t)HID * HID];     // Wo^T fp16
__device__ __align__(16) __half g_qh[(size_t)T_SEQ * HID];    // roped+scaled Q hi
__device__ __align__(16) __half g_ql[(size_t)T_SEQ * HID];
__device__ __align__(16) __half g_kh[(size_t)T_SEQ * 1024];   // roped K hi
__device__ __align__(16) __half g_kl[(size_t)T_SEQ * 1024];
__device__ __align__(16) __half g_vh[(size_t)T_SEQ * 1024];   // V hi
__device__ __align__(16) __half g_vl[(size_t)T_SEQ * 1024];

// ---------------------------------------------------------------------------
// helpers
// ---------------------------------------------------------------------------
__device__ __forceinline__ uint32_t smem_u32(const void* p) {
  uint32_t a;
  asm("{ .reg .u64 t; cvta.to.shared.u64 t, %1; cvt.u32.u64 %0, t; }"
      : "=r"(a) : "l"(p));
  return a;
}

__device__ __forceinline__ void cp16(uint32_t dst, const void* src) {
  asm volatile("cp.async.cg.shared.global [%0], [%1], 16;"
               :: "r"(dst), "l"(src) : "memory");
}

__device__ __forceinline__ void ldsm4(unsigned r[4], uint32_t addr) {
  asm volatile("ldmatrix.sync.aligned.m8n8.x4.shared.b16 {%0,%1,%2,%3}, [%4];"
               : "=r"(r[0]), "=r"(r[1]), "=r"(r[2]), "=r"(r[3]) : "r"(addr));
}

__device__ __forceinline__ void ldsm4t(unsigned r[4], uint32_t addr) {
  asm volatile("ldmatrix.sync.aligned.m8n8.x4.trans.shared.b16 {%0,%1,%2,%3}, [%4];"
               : "=r"(r[0]), "=r"(r[1]), "=r"(r[2]), "=r"(r[3]) : "r"(addr));
}

__device__ __forceinline__ void mma_f16(float d[4], const unsigned a[4],
                                        unsigned b0, unsigned b1) {
  asm volatile(
      "mma.sync.aligned.m16n8k16.row.col.f32.f16.f16.f32 "
      "{%0,%1,%2,%3}, {%4,%5,%6,%7}, {%8,%9}, {%0,%1,%2,%3};"
      : "+f"(d[0]), "+f"(d[1]), "+f"(d[2]), "+f"(d[3])
      : "r"(a[0]), "r"(a[1]), "r"(a[2]), "r"(a[3]), "r"(b0), "r"(b1));
}

__device__ __forceinline__ void split_store(__half* H, __half* L, size_t idx,
                                            float v) {
  __half h = __float2half_rn(v);
  H[idx] = h;
  L[idx] = __float2half_rn(v - __half2float(h));
}

// ---------------------------------------------------------------------------
// Prep kernels
// ---------------------------------------------------------------------------
__global__ void split_h(const float4* __restrict__ X, uint2* __restrict__ Xh,
                        uint2* __restrict__ Xl, int n4) {
  int i = blockIdx.x * 256 + threadIdx.x;
  if (i >= n4) return;
  float4 v = X[i];
  float hx = __half2float(__float2half_rn(v.x));
  float hy = __half2float(__float2half_rn(v.y));
  float hz = __half2float(__float2half_rn(v.z));
  float hw = __half2float(__float2half_rn(v.w));
  __half2 h0 = __floats2half2_rn(hx, hy), h1 = __floats2half2_rn(hz, hw);
  __half2 l0 = __floats2half2_rn(v.x - hx, v.y - hy);
  __half2 l1 = __floats2half2_rn(v.z - hz, v.w - hw);
  uint2 ho, lo;
  ho.x = *(unsigned*)&h0; ho.y = *(unsigned*)&h1;
  lo.x = *(unsigned*)&l0; lo.y = *(unsigned*)&l1;
  Xh[i] = ho;
  Xl[i] = lo;
}

__global__ void transpose_h(const float* __restrict__ W, __half* __restrict__ Wh,
                            int K, int N) {
  __shared__ float t[32][33];
  const int n0 = blockIdx.x << 5, k0 = blockIdx.y << 5;
  const int tx = threadIdx.x, ty = threadIdx.y;  // 32 x 8
#pragma unroll
  for (int i = 0; i < 32; i += 8)
    t[ty + i][tx] = W[(size_t)(k0 + ty + i) * N + n0 + tx];
  __syncthreads();
#pragma unroll
  for (int i = 0; i < 32; i += 8)
    Wh[(size_t)(n0 + ty + i) * K + k0 + tx] = __float2half_rn(t[tx][ty + i]);
}

// Fused RoPE + fp16 hi/lo conversion
__global__ void rope_convert(const float* __restrict__ qkv,
                             const int* __restrict__ positions) {
  const int t = blockIdx.x;
  const int tid = threadIdx.x;  // 256
  const float pos = (float)positions[t];
  const float* row = qkv + (size_t)t * QKV_N;

  for (int i = tid; i < 2048; i += 256) {
    int head = i >> 6, d = i & 63;
    float inv = expf(-((float)d * (1.0f / 64.0f)) * 13.815510557964274f);
    float fr = pos * inv;
    float c = cosf(fr), s = sinf(fr);
    float x1 = row[head * 128 + d], x2 = row[head * 128 + d + 64];
    size_t o = (size_t)t * 4096 + head * 128 + d;
    split_store(g_qh, g_ql, o,      (x1 * c - x2 * s) * ATTN_SCALE);
    split_store(g_qh, g_ql, o + 64, (x2 * c + x1 * s) * ATTN_SCALE);
  }
  for (int i = tid; i < 512; i += 256) {
    int head = i >> 6, d = i & 63;
    float inv = expf(-((float)d * (1.0f / 64.0f)) * 13.815510557964274f);
    float fr = pos * inv;
    float c = cosf(fr), s = sinf(fr);
    float x1 = row[4096 + head * 128 + d], x2 = row[4096 + head * 128 + d + 64];
    size_t o = (size_t)t * 1024 + head * 128 + d;
    split_store(g_kh, g_kl, o,      x1 * c - x2 * s);
    split_store(g_kh, g_kl, o + 64, x2 * c + x1 * s);
  }
  for (int i = tid; i < 1024; i += 256)
    split_store(g_vh, g_vl, (size_t)t * 1024 + i, row[5120 + i]);
}

// ---------------------------------------------------------------------------
// 2-term fp16 GEMM (proven: round-8). Two-pass MMA schedule, 4-stage cp.async,
// 2 CTAs/SM, 8 warps, warp tile 32x64.
// ---------------------------------------------------------------------------
__global__ __launch_bounds__(256, 2) void gemm_h2(
    const __half* __restrict__ pAh, const __half* __restrict__ pAl,
    const __half* __restrict__ pBh, float* __restrict__ C, int N, int K) {
  const uint32_t smb = smem_u32(dyn_smem);

  const int tid  = threadIdx.x;
  const int lane = tid & 31;
  const int warp = tid >> 5;
  const int wm = warp & 3;
  const int wn = warp >> 2;
  const int bm = blockIdx.y * 128;
  const int bn = blockIdx.x * 128;

  const __half* aH = pAh + (size_t)bm * K;
  const __half* aL = pAl + (size_t)bm * K;
  const __half* bH = pBh + (size_t)bn * K;

  const int crow = tid >> 1;
  const int cs0  = (tid & 1) << 1;
  const int csw  = (crow >> 1) & 3;
  const uint32_t cd0 = (uint32_t)(crow * 64 + ((cs0 ^ csw) << 4));
  const uint32_t cd1 = (uint32_t)(crow * 64 + (((cs0 + 1) ^ csw) << 4));
  const int cse = cs0 << 3;

  const int rowA = wm * 32 + (lane & 7) + ((lane >> 3) & 1) * 8;
  const int hcA  = (lane >> 4) & 1;
  const int swA  = (rowA >> 1) & 3;
  const uint32_t aofs = (uint32_t)(rowA * 64);
  const uint32_t xsa0 = (uint32_t)(((0 * 2 + hcA) ^ swA) << 4);
  const uint32_t xsa1 = (uint32_t)(((1 * 2 + hcA) ^ swA) << 4);

  const int rowB = wn * 64 + (lane & 7) + ((lane >> 4) & 1) * 8;
  const int hcB  = (lane >> 3) & 1;
  const int swB  = (rowB >> 1) & 3;
  const uint32_t bofs = (uint32_t)(rowB * 64);
  const uint32_t xsb0 = (uint32_t)(((0 * 2 + hcB) ^ swB) << 4);
  const uint32_t xsb1 = (uint32_t)(((1 * 2 + hcB) ^ swB) << 4);

  float acc[2][8][4];
#pragma unroll
  for (int i = 0; i < 2; i++)
#pragma unroll
    for (int j = 0; j < 8; j++)
#pragma unroll
      for (int r = 0; r < 4; r++) acc[i][j][r] = 0.f;

  const int NC = K >> 5;

#define ISSUE(c)                                                              \
  do {                                                                        \
    uint32_t sb = smb + (uint32_t)((c) & 3) * STG_BYTES;                      \
    size_t gg = (size_t)crow * K + ((c) << 5) + cse;                          \
    cp16(sb + cd0,              aH + gg); cp16(sb + cd1,              aH + gg + 8); \
    cp16(sb + TILE_B + cd0,     aL + gg); cp16(sb + TILE_B + cd1,     aL + gg + 8); \
    cp16(sb + 2 * TILE_B + cd0, bH + gg); cp16(sb + 2 * TILE_B + cd1, bH + gg + 8); \
    asm volatile("cp.async.commit_group;" ::: "memory");                      \
  } while (0)

  ISSUE(0);
  ISSUE(1);
  ISSUE(2);

  for (int c = 0; c < NC; ++c) {
    asm volatile("cp.async.wait_group 2;" ::: "memory");
    __syncthreads();
    if (c + 3 < NC) ISSUE(c + 3);

    const uint32_t sb  = smb + (uint32_t)(c & 3) * STG_BYTES;
    const uint32_t abh = sb + aofs;
    const uint32_t abl = abh + TILE_B;
    const uint32_t bbh = sb + 2 * TILE_B + bofs;

#pragma unroll
    for (int st = 0; st < 2; ++st) {
      const uint32_t xa = st ? xsa1 : xsa0;
      const uint32_t xb = st ? xsb1 : xsb0;
      unsigned af[2][4], bf[4][4];
      ldsm4(af[0], abh + xa);
      ldsm4(af[1], abh + 1024 + xa);
#pragma unroll
      for (int p = 0; p < 4; ++p) ldsm4(bf[p], bbh + p * 1024 + xb);
#pragma unroll
      for (int p = 0; p < 4; ++p)
#pragma unroll
        for (int mi = 0; mi < 2; ++mi)
#pragma unroll
          for (int sub = 0; sub < 2; ++sub)
            mma_f16(acc[mi][p * 2 + sub], af[mi], bf[p][sub * 2],
                    bf[p][sub * 2 + 1]);
      ldsm4(af[0], abl + xa);
      ldsm4(af[1], abl + 1024 + xa);
#pragma unroll
      for (int p = 0; p < 4; ++p)
#pragma unroll
        for (int mi = 0; mi < 2; ++mi)
#pragma unroll
          for (int sub = 0; sub < 2; ++sub)
            mma_f16(acc[mi][p * 2 + sub], af[mi], bf[p][sub * 2],
                    bf[p][sub * 2 + 1]);
    }
  }
#undef ISSUE

  const int g  = lane >> 2;
  const int tg = lane & 3;
#pragma unroll
  for (int mi = 0; mi < 2; mi++) {
    int r0 = bm + wm * 32 + mi * 16 + g;
#pragma unroll
    for (int ni = 0; ni < 8; ni++) {
      int c = bn + wn * 64 + ni * 8 + tg * 2;
      C[(size_t)r0 * N + c]           = acc[mi][ni][0];
      C[(size_t)r0 * N + c + 1]       = acc[mi][ni][1];
      C[(size_t)(r0 + 8) * N + c]     = acc[mi][ni][2];
      C[(size_t)(r0 + 8) * N + c + 1] = acc[mi][ni][3];
    }
  }
}

// ---------------------------------------------------------------------------
// Flash attention v3: 128-row Q tiles, 256 threads / 8 warps (16 rows each),
// double-buffered KV (2-stage cp.async pipeline), fp16 + ldmatrix throughout.
// ---------------------------------------------------------------------------
__global__ __launch_bounds__(256) void attn3(__half* __restrict__ oh,
                                             __half* __restrict__ ol) {
  char* smc = dyn_smem;
  const uint32_t smb = smem_u32(smc);

  const int h = blockIdx.x, qt = blockIdx.y;
  const int kvh = h >> 2;
  const int q0 = qt * 128;
  const int jmax = 2 * qt + 1;
  const int tid = threadIdx.x, lane = tid & 31, w = tid >> 5;
  const int g = lane >> 2, tg = lane & 3;

  // ---- Q tile load (once): 128 rows x 128 cols, hi+lo ----
  {
    const int row = tid >> 1, s0 = (tid & 1) * 8, rx = row & 7;
    const size_t gq = (size_t)(q0 + row) * 4096 + h * 128 + s0 * 8;
    const uint32_t dr = smb + row * 256;
#pragma unroll
    for (int s = 0; s < 8; ++s) {
      uint32_t d = dr + (((s0 + s) ^ rx) << 4);
      cp16(AQH + d, g_qh + gq + s * 8);
      cp16(AQL + d, g_ql + gq + s * 8);
    }
    asm volatile("cp.async.commit_group;" ::: "memory");
  }

  // KV issue helper values: thread -> (row 0..63, 4 of 16 segs)
  const int kvrow = tid >> 2, kvs0 = (tid & 3) * 4, kvrx = kvrow & 7;

#define KV_ISSUE(j, stg)                                                      \
  do {                                                                        \
    const uint32_t base = smb + AKV + (uint32_t)(stg) * 65536;                \
    const size_t gk = (size_t)((j) * 64 + kvrow) * 1024 + kvh * 128 + kvs0 * 8; \
    _Pragma("unroll")                                                         \
    for (int s = 0; s < 4; ++s) {                                             \
      uint32_t d = (uint32_t)(kvrow * 256 + (((kvs0 + s) ^ kvrx) << 4));      \
      cp16(base + d,         g_kh + gk + s * 8);                              \
      cp16(base + 16384 + d, g_kl + gk + s * 8);                              \
      cp16(base + 32768 + d, g_vh + gk + s * 8);                              \
      cp16(base + 49152 + d, g_vl + gk + s * 8);                              \
    }                                                                         \
    asm volatile("cp.async.commit_group;" ::: "memory");                      \
  } while (0)

  KV_ISSUE(0, 0);

  // fragment geometry (warp covers q rows [w*16, w*16+16))
  const int rowA = w * 16 + (lane & 7) + ((lane >> 3) & 1) * 8;
  const int rxA = lane & 7;
  const int hcA = (lane >> 4) & 1;
  const uint32_t aQ = smb + (uint32_t)rowA * 256;
  const uint32_t aP = smb + APS + (uint32_t)rowA * 128;
  const int rBb = (lane & 7) + ((lane >> 4) & 1) * 8;
  const int hcB = (lane >> 3) & 1;
  const int subm = lane >> 3;
  const int rV = (lane & 7) + ((subm & 1) << 3);
  const int hsV = subm >> 1;

  float m0 = -1e30f, m1 = -1e30f, l0 = 0.f, l1 = 0.f;
  float O[16][4];
#pragma unroll
  for (int i = 0; i < 16; i++)
#pragma unroll
    for (int r = 0; r < 4; r++) O[i][r] = 0.f;

  for (int j = 0; j <= jmax; ++j) {
    __syncthreads();  // buffer (j+1)&1 free (its consumer was compute j-1)
    if (j < jmax) {
      KV_ISSUE(j + 1, (j + 1) & 1);
      asm volatile("cp.async.wait_group 1;" ::: "memory");
    } else {
      asm volatile("cp.async.wait_group 0;" ::: "memory");
    }
    __syncthreads();

    const uint32_t kvb = smb + AKV + (uint32_t)(j & 1) * 65536;

    // ---- S = Qs K^T, 3-term fp16 ----
    float s[8][4];
#pragma unroll
    for (int ni = 0; ni < 8; ni++)
#pragma unroll
      for (int r = 0; r < 4; r++) s[ni][r] = 0.f;

#pragma unroll
    for (int kst = 0; kst < 8; ++kst) {
      unsigned qh[4], ql[4];
      const uint32_t xa = (uint32_t)(((kst * 2 + hcA) ^ rxA) << 4);
      ldsm4(qh, aQ + AQH + xa);
      ldsm4(ql, aQ + AQL + xa);
#pragma unroll
      for (int p = 0; p < 4; ++p) {
        const int rb = p * 16 + rBb;
        const uint32_t ab =
            kvb + (uint32_t)rb * 256 + (uint32_t)(((kst * 2 + hcB) ^ (rb & 7)) << 4);
        unsigned kh[4], kl[4];
        ldsm4(kh, ab);
        ldsm4(kl, ab + 16384);
        const int n0i = p * 2;
        mma_f16(s[n0i],     qh, kh[0], kh[1]);
        mma_f16(s[n0i + 1], qh, kh[2], kh[3]);
        mma_f16(s[n0i],     ql, kh[0], kh[1]);
        mma_f16(s[n0i + 1], ql, kh[2], kh[3]);
        mma_f16(s[n0i],     qh, kl[0], kl[1]);
        mma_f16(s[n0i + 1], qh, kl[2], kl[3]);
      }
    }

    // ---- online softmax ----
    const int gr0 = q0 + w * 16 + g;
    const int gr1 = gr0 + 8;
    float tm0 = -1e30f, tm1 = -1e30f;
#pragma unroll
    for (int ni = 0; ni < 8; ni++) {
#pragma unroll
      for (int cc = 0; cc < 2; cc++) {
        int gc = j * 64 + ni * 8 + tg * 2 + cc;
        float v0 = s[ni][cc];
        float v1 = s[ni][2 + cc];
        if (gc > gr0) v0 = -1e30f;
        if (gc > gr1) v1 = -1e30f;
        s[ni][cc] = v0;
        s[ni][2 + cc] = v1;
        tm0 = fmaxf(tm0, v0);
        tm1 = fmaxf(tm1, v1);
      }
    }
    tm0 = fmaxf(tm0, __shfl_xor_sync(0xffffffffu, tm0, 1));
    tm0 = fmaxf(tm0, __shfl_xor_sync(0xffffffffu, tm0, 2));
    tm1 = fmaxf(tm1, __shfl_xor_sync(0xffffffffu, tm1, 1));
    tm1 = fmaxf(tm1, __shfl_xor_sync(0xffffffffu, tm1, 2));

    float nm0 = fmaxf(m0, tm0), nm1 = fmaxf(m1, tm1);
    float a0 = __expf(m0 - nm0), a1 = __expf(m1 - nm1);

    const uint32_t pr0 = APS + (uint32_t)(w * 16 + g) * 128;
    const uint32_t pr1 = pr0 + 1024;
    float ps0 = 0.f, ps1 = 0.f;
#pragma unroll
    for (int ni = 0; ni < 8; ni++) {
      float p00 = __expf(s[ni][0] - nm0);
      float p01 = __expf(s[ni][1] - nm0);
      float p10 = __expf(s[ni][2] - nm1);
      float p11 = __expf(s[ni][3] - nm1);
      ps0 += p00 + p01;
      ps1 += p10 + p11;
      const uint32_t px = (uint32_t)(((ni ^ g) << 4) + tg * 4);
      *reinterpret_cast<__half2*>(smc + pr0 + px) = __floats2half2_rn(p00, p01);
      *reinterpret_cast<__half2*>(smc + pr1 + px) = __floats2half2_rn(p10, p11);
    }
    ps0 += __shfl_xor_sync(0xffffffffu, ps0, 1);
    ps0 += __shfl_xor_sync(0xffffffffu, ps0, 2);
    ps1 += __shfl_xor_sync(0xffffffffu, ps1, 1);
    ps1 += __shfl_xor_sync(0xffffffffu, ps1, 2);

    l0 = l0 * a0 + ps0;
    l1 = l1 * a1 + ps1;
    m0 = nm0;
    m1 = nm1;
#pragma unroll
    for (int ni = 0; ni < 16; ni++) {
      O[ni][0] *= a0; O[ni][1] *= a0;
      O[ni][2] *= a1; O[ni][3] *= a1;
    }
    __syncwarp();

    // ---- O += P (Vh + Vl), two passes ----
#pragma unroll
    for (int k2 = 0; k2 < 4; ++k2) {
      unsigned pf[4];
      ldsm4(pf, aP + (uint32_t)(((k2 * 2 + hcA) ^ rxA) << 4));
      const int rv = k2 * 16 + rV;
      const uint32_t vb = kvb + 32768 + (uint32_t)rv * 256;
      const int rxv = rv & 7;
      unsigned vf[8][4];
#pragma unroll
      for (int dg = 0; dg < 8; ++dg)
        ldsm4t(vf[dg], vb + (uint32_t)(((dg * 2 + hsV) ^ rxv) << 4));
#pragma unroll
      for (int dg = 0; dg < 8; ++dg) {
        mma_f16(O[dg * 2],     pf, vf[dg][0], vf[dg][1]);
        mma_f16(O[dg * 2 + 1], pf, vf[dg][2], vf[dg][3]);
      }
#pragma unroll
      for (int dg = 0; dg < 8; ++dg)
        ldsm4t(vf[dg], vb + 16384 + (uint32_t)(((dg * 2 + hsV) ^ rxv) << 4));
#pragma unroll
      for (int dg = 0; dg < 8; ++dg) {
        mma_f16(O[dg * 2],     pf, vf[dg][0], vf[dg][1]);
        mma_f16(O[dg * 2 + 1], pf, vf[dg][2], vf[dg][3]);
      }
    }
  }
#undef KV_ISSUE

  // epilogue -> fp16 hi/lo, half2 paired stores
  const float inv0 = 1.f / l0;
  const float inv1 = 1.f / l1;
  const int r0 = q0 + w * 16 + g;
#pragma unroll
  for (int ni = 0; ni < 16; ni++) {
    const int c = h * HD + ni * 8 + tg * 2;
    const size_t i0 = (size_t)r0 * HID + c;
    const size_t i1 = (size_t)(r0 + 8) * HID + c;
    float v00 = O[ni][0] * inv0, v01 = O[ni][1] * inv0;
    float v10 = O[ni][2] * inv1, v11 = O[ni][3] * inv1;
    __half2 h0 = __floats2half2_rn(v00, v01);
    __half2 h1 = __floats2half2_rn(v10, v11);
    *reinterpret_cast<__half2*>(oh + i0) = h0;
    *reinterpret_cast<__half2*>(oh + i1) = h1;
    *reinterpret_cast<__half2*>(ol + i0) =
        __floats2half2_rn(v00 - __half2float(__low2half(h0)),
                          v01 - __half2float(__high2half(h0)));
    *reinterpret_cast<__half2*>(ol + i1) =
        __floats2half2_rn(v10 - __half2float(__low2half(h1)),
                          v11 - __half2float(__high2half(h1)));
  }
}

// ---------------------------------------------------------------------------
// launch
// ---------------------------------------------------------------------------
extern "C" void kernel_launch(void* const* d_in, const int* in_sizes, int n_in,
                              void* d_out, int out_size) {
  (void)in_sizes; (void)n_in; (void)out_size;
  const int*   positions = (const int*)d_in[0];
  const float* hidden    = (const float*)d_in[1];
  const float* Wqkv      = (const float*)d_in[2];
  const float* Wo        = (const float*)d_in[3];
  float* out = (float*)d_out;

  float* qkv_p;
  __half *ah, *al, *wqh, *woh;
  cudaGetSymbolAddress((void**)&qkv_p, g_qkv);
  cudaGetSymbolAddress((void**)&ah, g_ah);
  cudaGetSymbolAddress((void**)&al, g_al);
  cudaGetSymbolAddress((void**)&wqh, g_wqh);
  cudaGetSymbolAddress((void**)&woh, g_woh);

  cudaFuncSetAttribute(gemm_h2, cudaFuncAttributeMaxDynamicSharedMemorySize,
                       GEMM_SMEM);
  cudaFuncSetAttribute(attn3, cudaFuncAttributeMaxDynamicSharedMemorySize,
                       ATTN_SMEM);

  // Prep
  transpose_h<<<dim3(QKV_N / 32, HID / 32), dim3(32, 8)>>>(Wqkv, wqh, HID, QKV_N);
  transpose_h<<<dim3(HID / 32, HID / 32), dim3(32, 8)>>>(Wo, woh, HID, HID);
  split_h<<<(T_SEQ * HID / 4 + 255) / 256, 256>>>(
      (const float4*)hidden, (uint2*)ah, (uint2*)al, T_SEQ * HID / 4);

  // 1) QKV projection
  gemm_h2<<<dim3(QKV_N / 128, T_SEQ / 128), 256, GEMM_SMEM>>>(
      ah, al, wqh, qkv_p, QKV_N, HID);
  // 2) RoPE + fp16 conversion
  rope_convert<<<T_SEQ, 256>>>(qkv_p, positions);
  // 3) Flash attention (writes fp16 hi/lo into g_ah/g_al)
  attn3<<<dim3(NHEADS, T_SEQ / 128), 256, ATTN_SMEM>>>(ah, al);
  // 4) Output projection
  gemm_h2<<<dim3(HID / 128, T_SEQ / 128), 256, GEMM_SMEM>>>(
      ah, al, woh, out, HID, HID);
}